// round 1
// baseline (speedup 1.0000x reference)
#include <cuda_runtime.h>
#include <cstdint>

// FastRotation: for each of N=262144 filters (5x5x5 fp32), build Rodrigues
// rotation R from (theta_v, theta), rotate the canonical [-1,1]^3 5x5x5 grid,
// and trilinear-sample the filter volume with zero padding.
//
// One warp per filter. Volume staged in shared memory (coalesced load),
// each lane computes 4 of the 125 output points. Pure HBM-streaming kernel.

#define WARPS_PER_BLOCK 8
#define THREADS_PER_BLOCK (WARPS_PER_BLOCK * 32)

__global__ __launch_bounds__(THREADS_PER_BLOCK)
void fastrot_kernel(const float* __restrict__ filt,
                    const float* __restrict__ theta_v,
                    const float* __restrict__ theta,
                    float* __restrict__ out,
                    int n)
{
    __shared__ float svol[WARPS_PER_BLOCK][128];  // 125 used, padded

    const int lane = threadIdx.x & 31;
    const int wb   = threadIdx.x >> 5;
    const int fidx = blockIdx.x * WARPS_PER_BLOCK + wb;
    if (fidx >= n) return;

    // ---- stage the 125-float volume into smem (coalesced) ----
    const float* f = filt + (size_t)fidx * 125;
    float* sv = svol[wb];
    {
        // lanes 0..31 cover [0,32,64,96] offsets; tail guarded
        sv[lane]      = f[lane];
        sv[lane + 32] = f[lane + 32];
        sv[lane + 64] = f[lane + 64];
        int i3 = lane + 96;
        if (i3 < 125) sv[i3] = f[i3];
    }
    __syncwarp();

    // ---- Rodrigues matrix (every lane, redundant; registers only) ----
    const float tvx = theta_v[3 * fidx + 0];
    const float tvy = theta_v[3 * fidx + 1];
    const float tvz = theta_v[3 * fidx + 2];
    const float th  = theta[fidx];

    const float nrm = sqrtf(tvx * tvx + tvy * tvy + tvz * tvz);
    const float inv = 1.0f / fmaxf(nrm, 1e-12f);
    const float vx = tvx * inv, vy = tvy * inv, vz = tvz * inv;

    float s, ct;
    sincosf(th, &s, &ct);
    const float c = 1.0f - ct;

    // R = I + s*m + c*m^2, with m the cross-product matrix of v.
    // m^2 entries written out explicitly.
    const float r00 = 1.0f + c * (-vz * vz - vy * vy);
    const float r01 = -s * vz + c * (vx * vy);
    const float r02 =  s * vy + c * (vx * vz);
    const float r10 =  s * vz + c * (vx * vy);
    const float r11 = 1.0f + c * (-vz * vz - vx * vx);
    const float r12 = -s * vx + c * (vy * vz);
    const float r20 = -s * vy + c * (vx * vz);
    const float r21 =  s * vx + c * (vy * vz);
    const float r22 = 1.0f + c * (-vy * vy - vx * vx);

    float* o = out + (size_t)fidx * 125;

    #pragma unroll
    for (int rep = 0; rep < 4; rep++) {
        const int p = lane + rep * 32;
        if (p >= 125) break;

        // p = i*25 + j*5 + l ; base point = (c[i], c[j], c[l]), c[k] = -1 + 0.5*k
        const int i = p / 25;
        const int r = p - i * 25;
        const int j = r / 5;
        const int l = r - j * 5;

        const float px = -1.0f + 0.5f * (float)i;
        const float py = -1.0f + 0.5f * (float)j;
        const float pz = -1.0f + 0.5f * (float)l;

        // grid_k = sum_j p_j * R[j][k]
        const float gx = px * r00 + py * r10 + pz * r20;
        const float gy = px * r01 + py * r11 + pz * r21;
        const float gz = px * r02 + py * r12 + pz * r22;

        // to pixel coordinates: (g + 1) * 0.5 * (5 - 1) = (g + 1) * 2
        const float x = (gx + 1.0f) * 2.0f;
        const float y = (gy + 1.0f) * 2.0f;
        const float z = (gz + 1.0f) * 2.0f;

        const float x0f = floorf(x), y0f = floorf(y), z0f = floorf(z);
        const float wx = x - x0f, wy = y - y0f, wz = z - z0f;
        const int x0 = (int)x0f, y0 = (int)y0f, z0 = (int)z0f;

        float acc = 0.0f;
        #pragma unroll
        for (int dz = 0; dz < 2; dz++) {
            const int   zi  = z0 + dz;
            const float wzc = dz ? wz : (1.0f - wz);
            if (zi < 0 || zi > 4) continue;
            #pragma unroll
            for (int dy = 0; dy < 2; dy++) {
                const int   yi  = y0 + dy;
                const float wyc = dy ? wy : (1.0f - wy);
                if (yi < 0 || yi > 4) continue;
                const float wzy = wzc * wyc;
                const int base = zi * 25 + yi * 5;
                #pragma unroll
                for (int dx = 0; dx < 2; dx++) {
                    const int xi = x0 + dx;
                    if (xi < 0 || xi > 4) continue;
                    const float wxc = dx ? wx : (1.0f - wx);
                    acc += wzy * wxc * sv[base + xi];
                }
            }
        }
        o[p] = acc;
    }
}

extern "C" void kernel_launch(void* const* d_in, const int* in_sizes, int n_in,
                              void* d_out, int out_size)
{
    const float* filt    = (const float*)d_in[0];
    const float* theta_v = (const float*)d_in[1];
    const float* theta   = (const float*)d_in[2];
    float* out           = (float*)d_out;

    const int n = in_sizes[2];  // theta has one element per filter

    const int blocks = (n + WARPS_PER_BLOCK - 1) / WARPS_PER_BLOCK;
    fastrot_kernel<<<blocks, THREADS_PER_BLOCK>>>(filt, theta_v, theta, out, n);
}

// round 2
// speedup vs baseline: 1.4151x; 1.4151x over previous
#include <cuda_runtime.h>
#include <cstdint>

// FastRotation: per-filter Rodrigues rotation of the canonical 5x5x5 grid +
// trilinear resample with zero padding.
//
// R2: branch-free inner loop via zero-padded 9x9x9 smem volume (tap indices
// span [-2,6] since |g| <= sqrt(3)), hoisted index decompose, fast intrinsics.
// One warp per filter; each lane produces 4 of 125 outputs.

#define WARPS_PER_BLOCK 8
#define TPB (WARPS_PER_BLOCK * 32)
#define PADV 736   // 9*9*9 = 729, padded to multiple of 4 floats (16B)

__global__ __launch_bounds__(TPB)
void fastrot_kernel(const float* __restrict__ filt,
                    const float* __restrict__ theta_v,
                    const float* __restrict__ theta,
                    float* __restrict__ out,
                    int n)
{
    __shared__ __align__(16) float svol[WARPS_PER_BLOCK][PADV];

    const int lane = threadIdx.x & 31;
    const int wb   = threadIdx.x >> 5;
    const int fidx = blockIdx.x * WARPS_PER_BLOCK + wb;
    if (fidx >= n) return;

    float* sv = svol[wb];

    // ---- zero-fill padded volume with vector stores (184 float4 / warp) ----
    {
        float4* sv4 = (float4*)sv;
        const float4 z4 = make_float4(0.f, 0.f, 0.f, 0.f);
        #pragma unroll
        for (int k = 0; k < 6; k++) {
            const int idx = lane + k * 32;
            if (idx < PADV / 4) sv4[idx] = z4;
        }
    }
    __syncwarp();

    // ---- stage filter into padded interior; remember base coords ----
    // filter value at linear p = i*25 + j*5 + l  -> padded (i+2, j+2, l+2)
    const float* f = filt + (size_t)fidx * 125;
    float pxr[4], pyr[4], pzr[4];
    #pragma unroll
    for (int rep = 0; rep < 4; rep++) {
        const int p = lane + rep * 32;
        if (p < 125) {
            const float v = f[p];
            const int i = p / 25;
            const int r = p - i * 25;
            const int j = r / 5;
            const int l = r - j * 5;
            sv[(i + 2) * 81 + (j + 2) * 9 + (l + 2)] = v;
            pxr[rep] = -1.0f + 0.5f * (float)i;
            pyr[rep] = -1.0f + 0.5f * (float)j;
            pzr[rep] = -1.0f + 0.5f * (float)l;
        }
    }

    // ---- Rodrigues matrix, pre-doubled (pixel = 2*g + 2) ----
    const float tvx = theta_v[3 * fidx + 0];
    const float tvy = theta_v[3 * fidx + 1];
    const float tvz = theta_v[3 * fidx + 2];
    const float th  = theta[fidx];

    const float inv = rsqrtf(fmaxf(tvx * tvx + tvy * tvy + tvz * tvz, 1e-24f));
    const float vx = tvx * inv, vy = tvy * inv, vz = tvz * inv;

    float s, ct;
    __sincosf(th, &s, &ct);
    const float c = 1.0f - ct;

    // R = I + s*m + c*m^2 ; store 2*R
    const float a00 = 2.0f * (1.0f + c * (-vz * vz - vy * vy));
    const float a01 = 2.0f * (-s * vz + c * (vx * vy));
    const float a02 = 2.0f * ( s * vy + c * (vx * vz));
    const float a10 = 2.0f * ( s * vz + c * (vx * vy));
    const float a11 = 2.0f * (1.0f + c * (-vz * vz - vx * vx));
    const float a12 = 2.0f * (-s * vx + c * (vy * vz));
    const float a20 = 2.0f * (-s * vy + c * (vx * vz));
    const float a21 = 2.0f * ( s * vx + c * (vy * vz));
    const float a22 = 2.0f * (1.0f + c * (-vy * vy - vx * vx));

    __syncwarp();

    float* o = out + (size_t)fidx * 125;

    #pragma unroll
    for (int rep = 0; rep < 4; rep++) {
        const int p = lane + rep * 32;
        if (p >= 125) break;

        const float px = pxr[rep], py = pyr[rep], pz = pzr[rep];

        // pixel coords: x = 2*gx + 2, gx = px*R00 + py*R10 + pz*R20, etc.
        const float x = fmaf(px, a00, fmaf(py, a10, fmaf(pz, a20, 2.0f)));
        const float y = fmaf(px, a01, fmaf(py, a11, fmaf(pz, a21, 2.0f)));
        const float z = fmaf(px, a02, fmaf(py, a12, fmaf(pz, a22, 2.0f)));

        const float xf = floorf(x), yf = floorf(y), zf = floorf(z);
        const float wx = x - xf,   wy = y - yf,   wz = z - zf;
        const int x0 = (int)xf, y0 = (int)yf, z0 = (int)zf;

        // padded base index: (z0+2)*81 + (y0+2)*9 + (x0+2)
        const float* q = sv + (z0 * 81 + y0 * 9 + x0 + 182);

        const float cx = 1.0f - wx, cy = 1.0f - wy, cz = 1.0f - wz;
        const float c00 = cz * cy, c01 = cz * wy, c10 = wz * cy, c11 = wz * wy;

        const float s00 = fmaf(q[ 1], wx, q[ 0] * cx);
        const float s01 = fmaf(q[10], wx, q[ 9] * cx);
        const float s10 = fmaf(q[82], wx, q[81] * cx);
        const float s11 = fmaf(q[91], wx, q[90] * cx);

        const float acc = fmaf(c11, s11, fmaf(c10, s10, fmaf(c01, s01, c00 * s00)));
        o[p] = acc;
    }
}

extern "C" void kernel_launch(void* const* d_in, const int* in_sizes, int n_in,
                              void* d_out, int out_size)
{
    const float* filt    = (const float*)d_in[0];
    const float* theta_v = (const float*)d_in[1];
    const float* theta   = (const float*)d_in[2];
    float* out           = (float*)d_out;

    const int n = in_sizes[2];  // one theta per filter

    const int blocks = (n + WARPS_PER_BLOCK - 1) / WARPS_PER_BLOCK;
    fastrot_kernel<<<blocks, TPB>>>(filt, theta_v, theta, out, n);
}